// round 12
// baseline (speedup 1.0000x reference)
#include <cuda_runtime.h>

#define NN 8192
#define DD 128
#define PP 256
#define KK 256
#define DEG 32
#define FF 16
#define INV_TEMP (1.0f / 0.07f)
#define FULL 0xffffffffu

// Scratch (__device__ globals; no allocations allowed)
__device__ float g_loss[PP];
__device__ int   g_count = 0;

__device__ __forceinline__ float warp_sum(float v) {
#pragma unroll
    for (int o = 16; o; o >>= 1) v += __shfl_xor_sync(FULL, v, o);
    return v;
}

__device__ __forceinline__ float dot4(float4 a, float4 b) {
    return a.x * b.x + a.y * b.y + a.z * b.z + a.w * b.w;
}

// ---------------------------------------------------------------------------
// Grid = PP = 256 blocks x 512 threads (16 warps). Block i = neighbor i.
//   warps 0-7  (half 0): term1  (rows = N(q),  ref = z_i) + mu_xy/pos/core
//   warps 8-15 (half 1): term2  (rows = N(i),  ref = z_q) + negative loss
// Per-half warp wh owns rows 4wh..4wh+3 (indices via ONE uniform int4 load).
// Row warps publish raw (nr, dr); the half's lead warp finishes mu and does
// the softmax with numerator/denominator as two interleaved shfl chains.
// term1+term2 meet IN-BLOCK -> align computed locally; block emits one
// fully weighted scalar. Last-arriving block sums 256 floats with one warp.
// ---------------------------------------------------------------------------
__global__ void __launch_bounds__(512)
fused_kernel(const float* __restrict__ z,
             const float* __restrict__ et,
             const float* __restrict__ ct,
             const float* __restrict__ core,
             const float* __restrict__ omega,
             const float* __restrict__ phi,
             const int* __restrict__ qidx,
             const int* __restrict__ neg_idxs,
             const int* __restrict__ nbr_idxs,
             const int* __restrict__ neighbors,
             float* __restrict__ out) {
    __shared__ float s_nr[2][DEG], s_dr[2][DEG], s_te[2][DEG];
    __shared__ float s_term[2];
    __shared__ float s_pc;      // pos + core (weighted)
    __shared__ float s_ng;      // negative loss (weighted)
    __shared__ bool  s_isLast;

    const int t = threadIdx.x, lane = t & 31, warp = t >> 5;
    const int half = warp >> 3, wh = warp & 7;
    const int i = blockIdx.x;

    // ---- level-0 scalars (broadcast loads, once per block) ----
    const int   q   = qidx[0];
    const int   nbr = nbr_idxs[i];
    const float ct0 = ct[0];
    const int   baseRow = half ? nbr : q;    // whose neighborhood
    const int   refRow  = half ? q : nbr;    // vector dotted against rows

    float cq = 0.f, ci = 0.f;
    if (t == 0) { cq = core[q]; ci = core[nbr]; }

    // ---- level-1: 4 row indices via ONE uniform LDG.128 ----
    const int4 ii4 = ((const int4*)(neighbors + baseRow * DEG))[wh];
    const float4 ref4 = ((const float4*)(z + (long long)refRow * DD))[lane];

    // lead-warp aux row: half0 -> z_q (mu_xy) ; half1 -> z_neg (negative)
    float4 aux4 = make_float4(0.f, 0.f, 0.f, 0.f);
    if (wh == 0) {
        const int auxRow = half ? neg_idxs[i] : q;
        aux4 = ((const float4*)(z + (long long)auxRow * DD))[lane];
    }

    // ---- level-2: the 4 rows + edge time (8-lane broadcast LDG) ----
    const int g = lane >> 3, sub = lane & 7;
    const int gRow = (g & 2) ? ((g & 1) ? ii4.w : ii4.z)
                             : ((g & 1) ? ii4.y : ii4.x);
    const float4 r0 = ((const float4*)(z + (long long)ii4.x * DD))[lane];
    const float4 r1 = ((const float4*)(z + (long long)ii4.y * DD))[lane];
    const float4 r2 = ((const float4*)(z + (long long)ii4.z * DD))[lane];
    const float4 r3 = ((const float4*)(z + (long long)ii4.w * DD))[lane];
    const float dtv = ct0 - et[(long long)baseRow * NN + gRow];

    // ---- time encoding: 8 lanes per dt, 2 sinusoid slots per lane ----
    {
        float p = __sinf(omega[1 + sub] * dtv + phi[1 + sub]);
        p += (sub < 7) ? __sinf(omega[9 + sub] * dtv + phi[9 + sub])
                       : (omega[0] * dtv + phi[0]);
        p += __shfl_xor_sync(FULL, p, 1);
        p += __shfl_xor_sync(FULL, p, 2);
        p += __shfl_xor_sync(FULL, p, 4);
        if (sub == 0) s_te[half][4 * wh + g] = p;
    }

    // ---- row partials: 8 independent interleaved reduction chains ----
    {
        float n0 = dot4(r0, r0), d0 = dot4(ref4, r0);
        float n1 = dot4(r1, r1), d1 = dot4(ref4, r1);
        float n2 = dot4(r2, r2), d2 = dot4(ref4, r2);
        float n3 = dot4(r3, r3), d3 = dot4(ref4, r3);
#pragma unroll
        for (int o = 16; o; o >>= 1) {
            n0 += __shfl_xor_sync(FULL, n0, o);
            d0 += __shfl_xor_sync(FULL, d0, o);
            n1 += __shfl_xor_sync(FULL, n1, o);
            d1 += __shfl_xor_sync(FULL, d1, o);
            n2 += __shfl_xor_sync(FULL, n2, o);
            d2 += __shfl_xor_sync(FULL, d2, o);
            n3 += __shfl_xor_sync(FULL, n3, o);
            d3 += __shfl_xor_sync(FULL, d3, o);
        }
        if (lane == 0) {
            const int j = 4 * wh;
            s_nr[half][j] = n0; s_dr[half][j] = d0;
            s_nr[half][j + 1] = n1; s_dr[half][j + 1] = d1;
            s_nr[half][j + 2] = n2; s_dr[half][j + 2] = d2;
            s_nr[half][j + 3] = n3; s_dr[half][j + 3] = d3;
        }
    }

    // ---- lead warps: ref/aux norms (3 interleaved chains) + extras ----
    float aref = 0.f, rref = 0.f;
    if (wh == 0) {
        float nf = dot4(ref4, ref4);
        float na = dot4(aux4, aux4);
        float da = dot4(aux4, ref4);
#pragma unroll
        for (int o = 16; o; o >>= 1) {
            nf += __shfl_xor_sync(FULL, nf, o);
            na += __shfl_xor_sync(FULL, na, o);
            da += __shfl_xor_sync(FULL, da, o);
        }
        rref = rsqrtf(fmaxf(nf, 1e-24f));
        aref = nf * rref * rref;                 // ||ref_hat||^2
        const float ra = rsqrtf(fmaxf(na, 1e-24f));
        const float aa = na * ra * ra;
        const float mu = -(aa + aref - 2.f * ra * rref * da);
        if (lane == 0) {
            const float sg = 1.f / (1.f + __expf(-mu));
            if (half == 0) {
                // mu = mu_xy (aux = z_q, ref = z_i) -> pos + core
                const float dc = ci - cq;
                s_pc = -__logf(sg + 1e-8f) * (1.f / PP)
                     + (0.1f / PP) * dc * dc;
            } else {
                // mu = negative-sample mu (aux = z_neg, ref = z_q)
                s_ng = -__logf(1.f - sg + 1e-8f) * (1.f / KK);
            }
        }
    }
    __syncthreads();  // publish s_nr/s_dr/s_te (+ s_pc/s_ng)

    // ---- softmax in each half's lead warp (has aref/rref) ----
    if (wh == 0) {
        const float nr = s_nr[half][lane], dr = s_dr[half][lane];
        const float rr = rsqrtf(fmaxf(nr, 1e-24f));
        const float mu = -(aref + nr * rr * rr - 2.f * rref * rr * dr);
        float w  = __expf(mu * INV_TEMP - s_te[half][lane]);
        float wm = w * mu;
#pragma unroll
        for (int o = 16; o; o >>= 1) {
            w  += __shfl_xor_sync(FULL, w,  o);
            wm += __shfl_xor_sync(FULL, wm, o);
        }
        if (lane == 0) s_term[half] = wm / (w + 1e-8f);  // == ref formula
    }
    __syncthreads();

    // ---- combine in-block: align needs term1+term2 (both local now) ----
    if (t == 0) {
        const float dd = s_term[0] + s_term[1];   // lambda_T - lambda_S
        const float ad = fabsf(dd);
        const float al = (ad < 1.f) ? 0.5f * dd * dd : (ad - 0.5f);
        g_loss[i] = s_pc + s_ng + al * (0.1f / PP);
        __threadfence();
        const int c = atomicAdd(&g_count, 1);
        s_isLast = (c == (int)gridDim.x - 1);
    }
    __syncthreads();

    // ---- last-arriving block: one warp sums 256 contiguous floats ----
    if (s_isLast && warp == 0) {
        __threadfence();
        float sv = 0.f;
#pragma unroll
        for (int k = 0; k < PP / 32; k++) sv += g_loss[lane + 32 * k];
        sv = warp_sum(sv);
        if (lane == 0) {
            out[0] = sv;
            g_count = 0;   // reset for next graph replay
        }
    }
}

// ---------------------------------------------------------------------------
// Inputs (metadata order):
// 0 z [N*D] f32, 1 edge_times [N*N] f32, 2 current_time [1] f32,
// 3 core_values [N] f32, 4 omega [F] f32, 5 phi [F] f32,
// 6 query_idx [1] i32, 7 neg_idxs [K] i32, 8 neighbor_idxs [P] i32,
// 9 neighbors [N*DEG] i32. Output: [1] f32.
// ---------------------------------------------------------------------------
extern "C" void kernel_launch(void* const* d_in, const int* in_sizes, int n_in,
                              void* d_out, int out_size) {
    const float* z     = (const float*)d_in[0];
    const float* et    = (const float*)d_in[1];
    const float* ct    = (const float*)d_in[2];
    const float* core  = (const float*)d_in[3];
    const float* omega = (const float*)d_in[4];
    const float* phi   = (const float*)d_in[5];
    const int*   qidx  = (const int*)d_in[6];
    const int*   negi  = (const int*)d_in[7];
    const int*   nbri  = (const int*)d_in[8];
    const int*   nbrs  = (const int*)d_in[9];

    fused_kernel<<<PP, 512>>>(z, et, ct, core, omega, phi,
                              qidx, negi, nbri, nbrs, (float*)d_out);
}

// round 13
// speedup vs baseline: 1.2316x; 1.2316x over previous
#include <cuda_runtime.h>

#define NN 8192
#define DD 128
#define PP 256
#define KK 256
#define DEG 32
#define FF 16
#define INV_TEMP (1.0f / 0.07f)
#define FULL 0xffffffffu

// Scratch (__device__ globals; no allocations allowed)
__device__ float g_t1[PP], g_t2[PP], g_posc[PP], g_neg[KK];
__device__ int   g_count = 0;

__device__ __forceinline__ float warp_sum(float v) {
#pragma unroll
    for (int o = 16; o; o >>= 1) v += __shfl_xor_sync(FULL, v, o);
    return v;
}

__device__ __forceinline__ float dot4(float4 a, float4 b) {
    return a.x * b.x + a.y * b.y + a.z * b.z + a.w * b.w;
}

// ---------------------------------------------------------------------------
// Grid = 2*PP = 512 blocks x 256 threads (8 warps).  (R11 champion shape)
//   block b in [0,PP):   term1 for neighbor i=b (+ mu_xy/pos/core in warp 0)
//   block b in [PP,2PP): term2 for neighbor i=b-PP (+ negative in warp 0)
// Warp w owns rows 4w..4w+3 (indices via ONE uniform int4 load). Row warps
// publish raw (nr, dr); warp 0 finishes mu and does the softmax with
// numerator/denominator as two interleaved shfl chains. ALL global stores
// come from warp 0 lane 0, so completion needs NO block-wide sync: lane 0
// fences+atomics, and the last block's warp 0 alone does the final reduce.
// ---------------------------------------------------------------------------
__global__ void __launch_bounds__(256)
fused_kernel(const float* __restrict__ z,
             const float* __restrict__ et,
             const float* __restrict__ ct,
             const float* __restrict__ core,
             const float* __restrict__ omega,
             const float* __restrict__ phi,
             const int* __restrict__ qidx,
             const int* __restrict__ neg_idxs,
             const int* __restrict__ nbr_idxs,
             const int* __restrict__ neighbors,
             float* __restrict__ out) {
    __shared__ float s_nr[DEG], s_dr[DEG], s_te[DEG];

    const int t = threadIdx.x, lane = t & 31, warp = t >> 5;
    const int b = blockIdx.x;
    const bool isT1 = (b < PP);
    const int  i = isT1 ? b : b - PP;

    // ---- level-0 scalars (broadcast loads) ----
    const int   q   = qidx[0];
    const int   nbr = nbr_idxs[i];
    const float ct0 = ct[0];
    const int   baseRow = isT1 ? q : nbr;   // whose neighborhood
    const int   refRow  = isT1 ? nbr : q;   // vector dotted against rows

    float cq = 0.f, ci = 0.f;
    if (isT1 && t == 0) { cq = core[q]; ci = core[nbr]; }

    // ---- level-1: 4 row indices via ONE uniform LDG.128 (no shfl chain) ----
    const int4 ii4 = ((const int4*)(neighbors + baseRow * DEG))[warp];
    const float4 ref4 = ((const float4*)(z + (long long)refRow * DD))[lane];

    // warp0 aux row: T1 -> z_q (mu_xy) ; T2 -> z_neg (negative loss)
    float4 aux4 = make_float4(0.f, 0.f, 0.f, 0.f);
    if (warp == 0) {
        const int auxRow = isT1 ? q : neg_idxs[i];
        aux4 = ((const float4*)(z + (long long)auxRow * DD))[lane];
    }

    // ---- level-2: edge time FIRST (DRAM, longest latency), then rows ----
    const int g = lane >> 3, sub = lane & 7;
    const int gRow = (g & 2) ? ((g & 1) ? ii4.w : ii4.z)
                             : ((g & 1) ? ii4.y : ii4.x);
    const float dtv = ct0 - et[(long long)baseRow * NN + gRow];
    const float4 r0 = ((const float4*)(z + (long long)ii4.x * DD))[lane];
    const float4 r1 = ((const float4*)(z + (long long)ii4.y * DD))[lane];
    const float4 r2 = ((const float4*)(z + (long long)ii4.z * DD))[lane];
    const float4 r3 = ((const float4*)(z + (long long)ii4.w * DD))[lane];

    // ---- time encoding: 8 lanes per dt, 2 sinusoid slots per lane ----
    {
        float p = __sinf(omega[1 + sub] * dtv + phi[1 + sub]);
        p += (sub < 7) ? __sinf(omega[9 + sub] * dtv + phi[9 + sub])
                       : (omega[0] * dtv + phi[0]);
        p += __shfl_xor_sync(FULL, p, 1);
        p += __shfl_xor_sync(FULL, p, 2);
        p += __shfl_xor_sync(FULL, p, 4);
        if (sub == 0) s_te[4 * warp + g] = p;
    }

    // ---- row partials: 8 independent interleaved reduction chains ----
    {
        float n0 = dot4(r0, r0), d0 = dot4(ref4, r0);
        float n1 = dot4(r1, r1), d1 = dot4(ref4, r1);
        float n2 = dot4(r2, r2), d2 = dot4(ref4, r2);
        float n3 = dot4(r3, r3), d3 = dot4(ref4, r3);
#pragma unroll
        for (int o = 16; o; o >>= 1) {
            n0 += __shfl_xor_sync(FULL, n0, o);
            d0 += __shfl_xor_sync(FULL, d0, o);
            n1 += __shfl_xor_sync(FULL, n1, o);
            d1 += __shfl_xor_sync(FULL, d1, o);
            n2 += __shfl_xor_sync(FULL, n2, o);
            d2 += __shfl_xor_sync(FULL, d2, o);
            n3 += __shfl_xor_sync(FULL, n3, o);
            d3 += __shfl_xor_sync(FULL, d3, o);
        }
        if (lane == 0) {
            const int j = 4 * warp;
            s_nr[j] = n0; s_dr[j] = d0;
            s_nr[j + 1] = n1; s_dr[j + 1] = d1;
            s_nr[j + 2] = n2; s_dr[j + 2] = d2;
            s_nr[j + 3] = n3; s_dr[j + 3] = d3;
        }
    }

    // ---- warp 0: ref/aux norms (3 interleaved chains) + extras ----
    float aref = 0.f, rref = 0.f;
    if (warp == 0) {
        float nf = dot4(ref4, ref4);
        float na = dot4(aux4, aux4);
        float da = dot4(aux4, ref4);
#pragma unroll
        for (int o = 16; o; o >>= 1) {
            nf += __shfl_xor_sync(FULL, nf, o);
            na += __shfl_xor_sync(FULL, na, o);
            da += __shfl_xor_sync(FULL, da, o);
        }
        rref = rsqrtf(fmaxf(nf, 1e-24f));
        aref = nf * rref * rref;                 // ||ref_hat||^2
        const float ra = rsqrtf(fmaxf(na, 1e-24f));
        const float aa = na * ra * ra;
        const float mu = -(aa + aref - 2.f * ra * rref * da);
        if (lane == 0) {
            const float sg = 1.f / (1.f + __expf(-mu));
            if (isT1) {
                // mu = mu_xy (aux = z_q, ref = z_i)
                const float dc = ci - cq;
                g_posc[i] = -__logf(sg + 1e-8f) * (1.f / PP)
                          + (0.1f / PP) * dc * dc;
            } else {
                // mu = negative-sample mu (aux = z_neg, ref = z_q)
                g_neg[i] = -__logf(1.f - sg + 1e-8f) * (1.f / KK);
            }
        }
    }
    __syncthreads();  // publish s_nr/s_dr/s_te

    // ---- warp 0 finishes: softmax + completion (no further block syncs) ----
    if (warp == 0) {
        const float nr = s_nr[lane], dr = s_dr[lane];
        const float rr = rsqrtf(fmaxf(nr, 1e-24f));
        const float mu = -(aref + nr * rr * rr - 2.f * rref * rr * dr);
        float w  = __expf(mu * INV_TEMP - s_te[lane]);
        float wm = w * mu;
#pragma unroll
        for (int o = 16; o; o >>= 1) {
            w  += __shfl_xor_sync(FULL, w,  o);
            wm += __shfl_xor_sync(FULL, wm, o);
        }
        int c = 0;
        if (lane == 0) {
            const float term = wm / (w + 1e-8f);   // == ref formula
            if (isT1) g_t1[i] = term;
            else      g_t2[i] = term;
            __threadfence();
            c = atomicAdd(&g_count, 1);
        }
        c = __shfl_sync(FULL, c, 0);

        // ---- last-arriving block: warp 0 alone reduces everything ----
        if (c == 2 * PP - 1) {
            __threadfence();
            float sv = 0.f;
#pragma unroll
            for (int k = 0; k < PP / 32; k++) {
                const int e = lane + 32 * k;
                const float dd = g_t1[e] + g_t2[e];   // lambda_T - lambda_S
                const float ad = fabsf(dd);
                const float al = (ad < 1.f) ? 0.5f * dd * dd : (ad - 0.5f);
                sv += g_posc[e] + g_neg[e] + al * (0.1f / PP);
            }
            sv = warp_sum(sv);
            if (lane == 0) {
                out[0] = sv;
                g_count = 0;   // reset for next graph replay
            }
        }
    }
}

// ---------------------------------------------------------------------------
// Inputs (metadata order):
// 0 z [N*D] f32, 1 edge_times [N*N] f32, 2 current_time [1] f32,
// 3 core_values [N] f32, 4 omega [F] f32, 5 phi [F] f32,
// 6 query_idx [1] i32, 7 neg_idxs [K] i32, 8 neighbor_idxs [P] i32,
// 9 neighbors [N*DEG] i32. Output: [1] f32.
// ---------------------------------------------------------------------------
extern "C" void kernel_launch(void* const* d_in, const int* in_sizes, int n_in,
                              void* d_out, int out_size) {
    const float* z     = (const float*)d_in[0];
    const float* et    = (const float*)d_in[1];
    const float* ct    = (const float*)d_in[2];
    const float* core  = (const float*)d_in[3];
    const float* omega = (const float*)d_in[4];
    const float* phi   = (const float*)d_in[5];
    const int*   qidx  = (const int*)d_in[6];
    const int*   negi  = (const int*)d_in[7];
    const int*   nbri  = (const int*)d_in[8];
    const int*   nbrs  = (const int*)d_in[9];

    fused_kernel<<<2 * PP, 256>>>(z, et, ct, core, omega, phi,
                                  qidx, negi, nbri, nbrs, (float*)d_out);
}